// round 2
// baseline (speedup 1.0000x reference)
#include <cuda_runtime.h>
#include <cstdint>

// Haar IDWT (reference's LH-uses-LPF-twice quirk folded into LL by linearity):
//   out[n,a,b] = 0.5 * ((ll+lh) + sb*hl + sa*sb*hh)
//   sa = (a even ? -1 : +1), sb likewise; (ll,lh,hl,hh) = in[n, a>>1, b>>1, :]
//
// One thread = 4 consecutive input pixels (one input row) -> 8x2 output block.
//   loads : 4x float4, front-batched (MLP_p1=4), 2KB contiguous per warp
//   stores: 2x float4 per output row x 2 rows, coalesced
// Streaming hints (.cs) on both: zero reuse, keep L2 from thrashing in the
// replay steady state.

namespace {
constexpr int B = 16;
constexpr int H = 512;
constexpr int W = 512;
constexpr int QUADS_PER_ROW = W / 4;                 // 128
constexpr int TOTAL = B * H * QUADS_PER_ROW;         // 1,048,576 threads
constexpr int OW4 = (2 * W) / 4;                     // 256 float4 per output row
}

__global__ void __launch_bounds__(256) idwt_haar_kernel(
    const float4* __restrict__ in, float4* __restrict__ out)
{
    int idx = blockIdx.x * blockDim.x + threadIdx.x;

    int q = idx & (QUADS_PER_ROW - 1);       // quad index 0..127
    int r = (idx >> 7) & (H - 1);            // input row 0..511
    int n = idx >> 16;                       // batch 0..15

    const float4* p = in + ((size_t)n * H + r) * W + 4 * q;
    float4 p0 = __ldcs(p + 0);
    float4 p1 = __ldcs(p + 1);
    float4 p2 = __ldcs(p + 2);
    float4 p3 = __ldcs(p + 3);

    float e0 = 0.5f * (p0.x + p0.y), hl0 = 0.5f * p0.z, hh0 = 0.5f * p0.w;
    float e1 = 0.5f * (p1.x + p1.y), hl1 = 0.5f * p1.z, hh1 = 0.5f * p1.w;
    float e2 = 0.5f * (p2.x + p2.y), hl2 = 0.5f * p2.z, hh2 = 0.5f * p2.w;
    float e3 = 0.5f * (p3.x + p3.y), hl3 = 0.5f * p3.z, hh3 = 0.5f * p3.w;

    // top row: a = 2r (even, sa=-1); even col sb=-1, odd col sb=+1
    float4 t0, t1, b0, b1;
    t0.x = e0 - hl0 + hh0;  t0.y = e0 + hl0 - hh0;
    t0.z = e1 - hl1 + hh1;  t0.w = e1 + hl1 - hh1;
    t1.x = e2 - hl2 + hh2;  t1.y = e2 + hl2 - hh2;
    t1.z = e3 - hl3 + hh3;  t1.w = e3 + hl3 - hh3;
    // bottom row: a = 2r+1 (odd, sa=+1)
    b0.x = e0 - hl0 - hh0;  b0.y = e0 + hl0 + hh0;
    b0.z = e1 - hl1 - hh1;  b0.w = e1 + hl1 + hh1;
    b1.x = e2 - hl2 - hh2;  b1.y = e2 + hl2 + hh2;
    b1.z = e3 - hl3 - hh3;  b1.w = e3 + hl3 + hh3;

    // output float4 index: row (2r) of image n, starting col 8q
    size_t o = ((size_t)n * 1024 + 2 * r) * OW4 + 2 * q;
    __stcs(out + o,           t0);
    __stcs(out + o + 1,       t1);
    __stcs(out + o + OW4,     b0);
    __stcs(out + o + OW4 + 1, b1);
}

extern "C" void kernel_launch(void* const* d_in, const int* in_sizes, int n_in,
                              void* d_out, int out_size)
{
    const float4* in = (const float4*)d_in[0];
    float4* out = (float4*)d_out;
    idwt_haar_kernel<<<TOTAL / 256, 256>>>(in, out);
}